// round 8
// baseline (speedup 1.0000x reference)
#include <cuda_runtime.h>
#include <cstdint>

#define B_   32
#define L_   1024
#define EMB_ 512
#define OUT_ 64
#define H_   8

// Scratch (device globals: allocation-free per harness rules)
__device__ float g_q[B_*H_*L_*OUT_];   // [b,h,l,o]
__device__ float g_k[B_*H_*L_*OUT_];   // [b,h,l,o]
__device__ float g_v[B_*H_*L_*OUT_];   // [b,h,l,o]
__device__ float g_c[B_*L_*H_*OUT_];   // concat [b,l,h*o]

// ===========================================================================
// tf32 warp-MMA helpers (baseline PTX, valid on plain sm_103 target)
// ===========================================================================
__device__ __forceinline__ uint32_t f2tf32(float x) {
    uint32_t r;
    asm("cvt.rna.tf32.f32 %0, %1;" : "=r"(r) : "f"(x));
    return r;
}
__device__ __forceinline__ uint32_t smem_u32(const void* p) {
    uint32_t a;
    asm("{ .reg .u64 t; cvta.to.shared.u64 t, %1; cvt.u32.u64 %0, t; }"
        : "=r"(a) : "l"(p));
    return a;
}
// D(16x8,f32) += A(16x8,tf32,row) * B(8x8,tf32,col)
__device__ __forceinline__ void mma8(float* d, const uint32_t* a, const uint32_t* b) {
    asm volatile(
        "mma.sync.aligned.m16n8k8.row.col.f32.tf32.tf32.f32 "
        "{%0,%1,%2,%3}, {%4,%5,%6,%7}, {%8,%9}, {%0,%1,%2,%3};"
        : "+f"(d[0]), "+f"(d[1]), "+f"(d[2]), "+f"(d[3])
        : "r"(a[0]), "r"(a[1]), "r"(a[2]), "r"(a[3]), "r"(b[0]), "r"(b[1]));
}
// ldmatrix x4: four 8x4-tf32 tiles; lane l of tile -> (row=l>>2, word=l&3).
// Matches mma A-frag (a0..a3) and (for row-major-as-transposed tiles) B-frags.
__device__ __forceinline__ void ldsm4(uint32_t* r, uint32_t addr) {
    asm volatile("ldmatrix.sync.aligned.m8n8.x4.shared.b16 {%0,%1,%2,%3}, [%4];"
        : "=r"(r[0]), "=r"(r[1]), "=r"(r[2]), "=r"(r[3]) : "r"(addr));
}
// Fragment maps (g = lane>>2, t = lane&3):
//   A m16k8: a0=(g,t) a1=(g+8,t) a2=(g,t+4) a3=(g+8,t+4)
//   B k8n8 (col): b0=(k=t,col=g) b1=(k=t+4,col=g)
//   D m16n8: d0=(g,2t) d1=(g,2t+1) d2=(g+8,2t) d3=(g+8,2t+1)

// ---------------------------------------------------------------------------
// Kernel 1: fused QKV projection as ONE GEMM over N=1536.
// Grid (256, 12): nb -> mat = nb>>2, heads h0=(nb&3)*2 (+1).  Block 128x128.
// 8 warps = 2(M) x 4(N), warp tile 64x32. K chunks of 32.
// SMEM: chunk-swizzled (phys_chunk = kc ^ (row&7)) rows of 32 tf32.
// ---------------------------------------------------------------------------
__global__ __launch_bounds__(256, 1) void qkv_tc(
    const float* __restrict__ joint,
    const float* __restrict__ Wq, const float* __restrict__ Wk, const float* __restrict__ Wv,
    const float* __restrict__ bq, const float* __restrict__ bk, const float* __restrict__ bv)
{
    const int mb  = blockIdx.x;
    const int nb  = blockIdx.y;
    const int mat = nb >> 2, h0 = (nb & 3) * 2;

    const float* W; const float* bias; float* outg;
    if (mat == 0)      { W = Wq; bias = bq; outg = g_q; }
    else if (mat == 1) { W = Wk; bias = bk; outg = g_k; }
    else               { W = Wv; bias = bv; outg = g_v; }

    __shared__ uint32_t As[128*32];   // [row][32k] swizzled
    __shared__ uint32_t Bt[128*32];   // [n][32k]  swizzled (B transposed)
    const uint32_t as_b = smem_u32(As), bt_b = smem_u32(Bt);

    const int tid  = threadIdx.x;
    const int wid  = tid >> 5, lane = tid & 31;
    const int g    = lane >> 2, t = lane & 3;
    const int wm   = (wid & 1)  * 64;
    const int wn   = (wid >> 1) * 32;

    float acc[4][4][4];
    #pragma unroll
    for (int i = 0; i < 4; i++)
        #pragma unroll
        for (int j = 0; j < 4; j++)
            #pragma unroll
            for (int r = 0; r < 4; r++) acc[i][j][r] = 0.f;

    const float* Arow = joint + (size_t)mb * 128 * EMB_;

    for (int kb = 0; kb < EMB_; kb += 32) {
        // A: 128 rows x 8 chunks, one float4 per task
        #pragma unroll
        for (int p = 0; p < 4; p++) {
            int task = tid + p*256;
            int row = task >> 3, kc = task & 7;
            float4 v = *(const float4*)(Arow + row*EMB_ + kb + kc*4);
            uint32_t* dst = As + row*32 + ((kc ^ (row & 7)) << 2);
            dst[0] = f2tf32(v.x); dst[1] = f2tf32(v.y);
            dst[2] = f2tf32(v.z); dst[3] = f2tf32(v.w);
        }
        // Bt: column n, 4 k values (strided global, coalesced across lanes)
        #pragma unroll
        for (int p = 0; p < 4; p++) {
            int task = tid + p*256;
            int n = task & 127, kc = task >> 7;
            int h = h0 + (n >> 6), o = n & 63;
            const float* wp = W + ((size_t)h*EMB_ + kb + kc*4)*OUT_ + o;
            uint32_t* dst = Bt + n*32 + ((kc ^ (n & 7)) << 2);
            dst[0] = f2tf32(wp[0]);       dst[1] = f2tf32(wp[OUT_]);
            dst[2] = f2tf32(wp[2*OUT_]);  dst[3] = f2tf32(wp[3*OUT_]);
        }
        __syncthreads();

        #pragma unroll
        for (int ks = 0; ks < 4; ks++) {
            uint32_t a[4][4], b[4][2];
            #pragma unroll
            for (int i = 0; i < 4; i++) {
                int row = wm + i*16 + (lane & 15);
                int kc  = ks*2 + (lane >> 4);
                ldsm4(a[i], as_b + ((row*32 + ((kc ^ (row & 7)) << 2)) << 2));
            }
            #pragma unroll
            for (int jj = 0; jj < 2; jj++) {
                int n  = wn + (jj*2 + (lane >> 4))*8 + (lane & 7);
                int kc = ks*2 + ((lane >> 3) & 1);
                uint32_t r[4];
                ldsm4(r, bt_b + ((n*32 + ((kc ^ (n & 7)) << 2)) << 2));
                b[jj*2][0]   = r[0]; b[jj*2][1]   = r[1];
                b[jj*2+1][0] = r[2]; b[jj*2+1][1] = r[3];
            }
            #pragma unroll
            for (int i = 0; i < 4; i++)
                #pragma unroll
                for (int j = 0; j < 4; j++)
                    mma8(acc[i][j], a[i], b[j]);
        }
        __syncthreads();
    }

    // Epilogue: + bias, store to per-mat tensor [b,h,l,o]
    #pragma unroll
    for (int i = 0; i < 4; i++) {
        #pragma unroll
        for (int half = 0; half < 2; half++) {
            int m = mb*128 + wm + i*16 + g + half*8;
            int bb = m >> 10, l = m & 1023;
            #pragma unroll
            for (int j = 0; j < 4; j++) {
                int col = wn + j*8 + t*2;
                int h = h0 + (col >> 6), o = col & 63;
                float2 r;
                r.x = acc[i][j][half*2+0] + __ldg(bias + h*OUT_ + o);
                r.y = acc[i][j][half*2+1] + __ldg(bias + h*OUT_ + o + 1);
                *(float2*)(outg + ((size_t)(bb*H_ + h)*L_ + l)*OUT_ + o) = r;
            }
        }
    }
}

// ---------------------------------------------------------------------------
// Kernel 2: attention, tf32 MMA + ldmatrix. Block = one (b,h) x 128 q-rows.
// 8 warps: S 4(M)x2(N) (warp 32x64), O 4(M)x2(N) (warp 32x32).
// Q fragments hoisted to registers (loaded once; Q staging aliases P region).
// V stored transposed [o][key] so PV B-frags come from ldmatrix.
// ---------------------------------------------------------------------------
#define PS_OFF 0                      // P [128 rows][128 k]  64KB (Q staging aliases)
#define KS_OFF 65536                  // K [128 key][64 k]    32KB
#define VT_OFF 98304                  // Vt [64 o][128 key]   32KB
#define LB_OFF 131072                 // l partials [128][2]  1KB
#define SMEM_ATTN 132096

__global__ __launch_bounds__(256, 1) void attn_tc(const int* __restrict__ traj)
{
    extern __shared__ char smem[];
    uint32_t* Ps = (uint32_t*)(smem + PS_OFF);
    uint32_t* Ks = (uint32_t*)(smem + KS_OFF);
    uint32_t* Vt = (uint32_t*)(smem + VT_OFF);
    float*    Lb = (float*)(smem + LB_OFF);
    const uint32_t ps_b = smem_u32(Ps), ks_b = smem_u32(Ks), vt_b = smem_u32(Vt);

    const int qb = blockIdx.x;          // 8 q-tiles of 128 rows
    const int bh = blockIdx.y;          // 256
    const int b  = bh >> 3, h = bh & 7;

    const int tid  = threadIdx.x;
    const int wid  = tid >> 5, lane = tid & 31;
    const int g    = lane >> 2, t = lane & 3;
    const int wm   = (wid >> 1) * 32;   // M stripe (S and O)
    const int wnS  = (wid & 1)  * 64;   // S columns
    const int wnO  = (wid & 1)  * 32;   // O columns

    // traj_len dtype sniff (int64 -> odd int32 words zero; values < 1024)
    int is64 = 1;
    #pragma unroll
    for (int i = 1; i < 32; i += 2) is64 &= (traj[i] == 0);
    const int T = is64 ? traj[2*b] : traj[b];

    const float scale = 0.044194173824159216f;  // 1/sqrt(512)

    // Stage Q [128,64] (scaled, tf32) into Ps region, chunk-swizzled
    const float* Qg = g_q + (size_t)bh * L_ * OUT_ + (size_t)(qb*128) * OUT_;
    #pragma unroll
    for (int p = 0; p < 8; p++) {
        int task = tid + p*256;
        int row = task >> 4, kc = task & 15;
        float4 v = *(const float4*)(Qg + row*64 + kc*4);
        uint32_t* dst = Ps + row*64 + ((kc ^ (row & 7)) << 2);
        dst[0] = f2tf32(v.x*scale); dst[1] = f2tf32(v.y*scale);
        dst[2] = f2tf32(v.z*scale); dst[3] = f2tf32(v.w*scale);
    }
    __syncthreads();

    // Hoist Q fragments: [i=2 m16 tiles][8 ks][4 regs]
    uint32_t qf[2][8][4];
    #pragma unroll
    for (int i = 0; i < 2; i++)
        #pragma unroll
        for (int ks = 0; ks < 8; ks++) {
            int row = wm + i*16 + (lane & 15);
            int kc  = ks*2 + (lane >> 4);
            ldsm4(qf[i][ks], ps_b + ((row*64 + ((kc ^ (row & 7)) << 2)) << 2));
        }
    __syncthreads();   // Q reads complete before P overwrites the region

    float oacc[2][4][4];
    #pragma unroll
    for (int i = 0; i < 2; i++)
        #pragma unroll
        for (int j = 0; j < 4; j++)
            #pragma unroll
            for (int r = 0; r < 4; r++) oacc[i][j][r] = 0.f;
    float lp[2][2] = {{0.f,0.f},{0.f,0.f}};
    bool qv[2][2];
    #pragma unroll
    for (int i = 0; i < 2; i++) {
        qv[i][0] = (qb*128 + wm + i*16 + g)     < T;
        qv[i][1] = (qb*128 + wm + i*16 + g + 8) < T;
    }

    const float* Kg = g_k + (size_t)bh * L_ * OUT_;
    const float* Vg = g_v + (size_t)bh * L_ * OUT_;

    for (int kb = 0; kb < L_; kb += 128) {
        // K tile [128 key][64 k]
        #pragma unroll
        for (int p = 0; p < 8; p++) {
            int task = tid + p*256;
            int key = task >> 4, kc = task & 15;
            float4 v = *(const float4*)(Kg + (size_t)(kb + key)*64 + kc*4);
            uint32_t* dst = Ks + key*64 + ((kc ^ (key & 7)) << 2);
            dst[0] = f2tf32(v.x); dst[1] = f2tf32(v.y);
            dst[2] = f2tf32(v.z); dst[3] = f2tf32(v.w);
        }
        // V transposed -> Vt [64 o][128 key]
        #pragma unroll
        for (int p = 0; p < 8; p++) {
            int task = tid + p*256;
            int key = task >> 4, o4 = task & 15;
            float4 v = *(const float4*)(Vg + (size_t)(kb + key)*64 + o4*4);
            int kcv = key >> 2, kr = key & 3;
            float vv[4] = {v.x, v.y, v.z, v.w};
            #pragma unroll
            for (int e = 0; e < 4; e++) {
                int o = o4*4 + e;
                Vt[o*128 + ((kcv ^ (o & 7)) << 2) + kr] = f2tf32(vv[e]);
            }
        }
        __syncthreads();

        // S = Q K^T : warp 32(M) x 64(N), k = 64
        float sacc[2][8][4];
        #pragma unroll
        for (int i = 0; i < 2; i++)
            #pragma unroll
            for (int j = 0; j < 8; j++)
                #pragma unroll
                for (int r = 0; r < 4; r++) sacc[i][j][r] = 0.f;

        #pragma unroll
        for (int ks = 0; ks < 8; ks++) {
            uint32_t bk[8][2];
            #pragma unroll
            for (int jj = 0; jj < 4; jj++) {
                int key = wnS + (jj*2 + (lane >> 4))*8 + (lane & 7);
                int kc  = ks*2 + ((lane >> 3) & 1);
                uint32_t r[4];
                ldsm4(r, ks_b + ((key*64 + ((kc ^ (key & 7)) << 2)) << 2));
                bk[jj*2][0]   = r[0]; bk[jj*2][1]   = r[1];
                bk[jj*2+1][0] = r[2]; bk[jj*2+1][1] = r[3];
            }
            #pragma unroll
            for (int i = 0; i < 2; i++)
                #pragma unroll
                for (int j = 0; j < 8; j++)
                    mma8(sacc[i][j], qf[i][ks], bk[j]);
        }

        // mask + exp, accumulate l, store P (v2, swizzled)
        #pragma unroll
        for (int j = 0; j < 8; j++) {
            int col = wnS + j*8 + t*2;
            bool kv0 = (kb + col)     < T;
            bool kv1 = (kb + col + 1) < T;
            #pragma unroll
            for (int i = 0; i < 2; i++) {
                #pragma unroll
                for (int half = 0; half < 2; half++) {
                    int row = wm + i*16 + g + half*8;
                    float p0 = __expf((qv[i][half] && kv0) ? sacc[i][j][half*2+0] : 0.f);
                    float p1 = __expf((qv[i][half] && kv1) ? sacc[i][j][half*2+1] : 0.f);
                    lp[i][half] += p0 + p1;
                    uint32_t* dst = Ps + row*128 + (((col >> 2) ^ (row & 7)) << 2) + (col & 3);
                    dst[0] = f2tf32(p0);
                    dst[1] = f2tf32(p1);
                }
            }
        }
        __syncthreads();   // P complete before PV

        // O += P V : warp 32(M) x 32(N), k = 128
        #pragma unroll
        for (int ks = 0; ks < 16; ks++) {
            uint32_t pa[2][4], vb[4][2];
            #pragma unroll
            for (int i = 0; i < 2; i++) {
                int row = wm + i*16 + (lane & 15);
                int kc  = ks*2 + (lane >> 4);
                ldsm4(pa[i], ps_b + ((row*128 + ((kc ^ (row & 7)) << 2)) << 2));
            }
            #pragma unroll
            for (int jj = 0; jj < 2; jj++) {
                int o  = wnO + (jj*2 + (lane >> 4))*8 + (lane & 7);
                int kc = ks*2 + ((lane >> 3) & 1);
                uint32_t r[4];
                ldsm4(r, vt_b + ((o*128 + ((kc ^ (o & 7)) << 2)) << 2));
                vb[jj*2][0]   = r[0]; vb[jj*2][1]   = r[1];
                vb[jj*2+1][0] = r[2]; vb[jj*2+1][1] = r[3];
            }
            #pragma unroll
            for (int i = 0; i < 2; i++)
                #pragma unroll
                for (int j = 0; j < 4; j++)
                    mma8(oacc[i][j], pa[i], vb[j]);
        }
        __syncthreads();   // PV reads done before next tile overwrite
    }

    // Reduce l within quad, publish across the two N-col warps
    #pragma unroll
    for (int i = 0; i < 2; i++)
        #pragma unroll
        for (int half = 0; half < 2; half++) {
            float v = lp[i][half];
            v += __shfl_xor_sync(0xffffffffu, v, 1);
            v += __shfl_xor_sync(0xffffffffu, v, 2);
            if (t == 0) Lb[(wm + i*16 + g + half*8)*2 + (wid & 1)] = v;
        }
    __syncthreads();

    // Normalize O and store concat [b,l,h*o]
    #pragma unroll
    for (int i = 0; i < 2; i++) {
        #pragma unroll
        for (int half = 0; half < 2; half++) {
            int row = wm + i*16 + g + half*8;
            float inv = 1.0f / (Lb[row*2] + Lb[row*2+1]);
            int q = qb*128 + row;
            float* dst = g_c + ((size_t)(b*L_ + q)*H_ + h) * OUT_;
            #pragma unroll
            for (int j = 0; j < 4; j++) {
                int col = wnO + j*8 + t*2;
                float2 r;
                r.x = oacc[i][j][half*2+0] * inv;
                r.y = oacc[i][j][half*2+1] * inv;
                *(float2*)(dst + col) = r;
            }
        }
    }
}

// ---------------------------------------------------------------------------
// Kernel 3: output projection  concat[32768,512] @ Wo[512,64], tf32 MMA.
// ---------------------------------------------------------------------------
__global__ __launch_bounds__(256) void out_tc(
    const float* __restrict__ Wo, float* __restrict__ outp)
{
    const int mb = blockIdx.x;

    __shared__ uint32_t As[128][36];
    __shared__ uint32_t Bs[32][72];

    const int tid  = threadIdx.x;
    const int wid  = tid >> 5, lane = tid & 31;
    const int g    = lane >> 2, t = lane & 3;
    const int wm   = (wid & 3) * 32;
    const int wn   = (wid >> 2) * 32;

    float acc[2][4][4];
    #pragma unroll
    for (int i = 0; i < 2; i++)
        #pragma unroll
        for (int j = 0; j < 4; j++)
            #pragma unroll
            for (int r = 0; r < 4; r++) acc[i][j][r] = 0.f;

    const float* Abase = g_c + (size_t)mb * 128 * (H_*OUT_);

    for (int kb = 0; kb < H_*OUT_; kb += 32) {
        #pragma unroll
        for (int f = tid; f < 1024; f += 256) {
            int row = f >> 3, c4 = (f & 7) << 2;
            float4 v = *(const float4*)(Abase + row * (H_*OUT_) + kb + c4);
            As[row][c4+0] = f2tf32(v.x); As[row][c4+1] = f2tf32(v.y);
            As[row][c4+2] = f2tf32(v.z); As[row][c4+3] = f2tf32(v.w);
        }
        #pragma unroll
        for (int f = tid; f < 512; f += 256) {
            int row = f >> 4, c4 = (f & 15) << 2;
            float4 v = *(const float4*)(Wo + (kb + row) * OUT_ + c4);
            Bs[row][c4+0] = f2tf32(v.x); Bs[row][c4+1] = f2tf32(v.y);
            Bs[row][c4+2] = f2tf32(v.z); Bs[row][c4+3] = f2tf32(v.w);
        }
        __syncthreads();

        #pragma unroll
        for (int ks = 0; ks < 4; ks++) {
            const int k0 = ks * 8;
            uint32_t a[2][4], b[4][2];
            #pragma unroll
            for (int i = 0; i < 2; i++) {
                int r0 = wm + i*16 + g;
                a[i][0] = As[r0][k0 + t];     a[i][1] = As[r0+8][k0 + t];
                a[i][2] = As[r0][k0 + t + 4]; a[i][3] = As[r0+8][k0 + t + 4];
            }
            #pragma unroll
            for (int j = 0; j < 4; j++) {
                int c = wn + j*8 + g;
                b[j][0] = Bs[k0 + t][c];
                b[j][1] = Bs[k0 + t + 4][c];
            }
            #pragma unroll
            for (int i = 0; i < 2; i++)
                #pragma unroll
                for (int j = 0; j < 4; j++)
                    mma8(acc[i][j], a[i], b[j]);
        }
        __syncthreads();
    }

    #pragma unroll
    for (int i = 0; i < 2; i++) {
        #pragma unroll
        for (int half = 0; half < 2; half++) {
            int m = mb*128 + wm + i*16 + g + half*8;
            float* dst = outp + (size_t)m * OUT_;
            #pragma unroll
            for (int j = 0; j < 4; j++) {
                int c = wn + j*8 + t*2;
                float2 r;
                r.x = acc[i][j][half*2+0];
                r.y = acc[i][j][half*2+1];
                *(float2*)(dst + c) = r;
            }
        }
    }
}

// ---------------------------------------------------------------------------
extern "C" void kernel_launch(void* const* d_in, const int* in_sizes, int n_in,
                              void* d_out, int out_size)
{
    const float* joint = (const float*)d_in[0];
    // d_in[1] = delta [B,L,L,2] -- unused by the reference math (mask shape only)
    const int*   traj  = (const int*)d_in[2];
    const float* Wq    = (const float*)d_in[3];
    const float* Wk    = (const float*)d_in[4];
    const float* Wv    = (const float*)d_in[5];
    const float* bq    = (const float*)d_in[6];
    const float* bk    = (const float*)d_in[7];
    const float* bv    = (const float*)d_in[8];
    const float* Wo    = (const float*)d_in[9];
    float* out = (float*)d_out;

    static int attr_set = 0;
    if (!attr_set) {
        cudaFuncSetAttribute(attn_tc,
            cudaFuncAttributeMaxDynamicSharedMemorySize, SMEM_ATTN);
        attr_set = 1;
    }

    dim3 g1(256, 12);
    qkv_tc<<<g1, 256>>>(joint, Wq, Wk, Wv, bq, bk, bv);

    dim3 g2(8, 256);
    attn_tc<<<g2, 256, SMEM_ATTN>>>(traj);

    out_tc<<<256, 256>>>(Wo, out);
}

// round 11
// speedup vs baseline: 1.1369x; 1.1369x over previous
#include <cuda_runtime.h>
#include <cstdint>

#define B_   32
#define L_   1024
#define EMB_ 512
#define OUT_ 64
#define H_   8

// Scratch (device globals: allocation-free per harness rules)
// g_q/g_k/g_v/g_c hold tf32-pre-rounded fp32 bit patterns (g_q also pre-scaled).
__device__ float g_q[B_*H_*L_*OUT_];   // [b,h,l,o]
__device__ float g_k[B_*H_*L_*OUT_];   // [b,h,l,o]
__device__ float g_v[B_*H_*L_*OUT_];   // [b,h,l,o]
__device__ float g_c[B_*L_*H_*OUT_];   // concat [b,l,h*o]

// ===========================================================================
// tf32 warp-MMA helpers (baseline PTX, valid on plain sm_103 target)
// ===========================================================================
__device__ __forceinline__ uint32_t f2tf32(float x) {
    uint32_t r;
    asm("cvt.rna.tf32.f32 %0, %1;" : "=r"(r) : "f"(x));
    return r;
}
__device__ __forceinline__ uint32_t smem_u32(const void* p) {
    uint32_t a;
    asm("{ .reg .u64 t; cvta.to.shared.u64 t, %1; cvt.u32.u64 %0, t; }"
        : "=r"(a) : "l"(p));
    return a;
}
// D(16x8,f32) += A(16x8,tf32,row) * B(8x8,tf32,col)
__device__ __forceinline__ void mma8(float* d, const uint32_t* a, const uint32_t* b) {
    asm volatile(
        "mma.sync.aligned.m16n8k8.row.col.f32.tf32.tf32.f32 "
        "{%0,%1,%2,%3}, {%4,%5,%6,%7}, {%8,%9}, {%0,%1,%2,%3};"
        : "+f"(d[0]), "+f"(d[1]), "+f"(d[2]), "+f"(d[3])
        : "r"(a[0]), "r"(a[1]), "r"(a[2]), "r"(a[3]), "r"(b[0]), "r"(b[1]));
}
__device__ __forceinline__ void ldsm4(uint32_t* r, uint32_t addr) {
    asm volatile("ldmatrix.sync.aligned.m8n8.x4.shared.b16 {%0,%1,%2,%3}, [%4];"
        : "=r"(r[0]), "=r"(r[1]), "=r"(r[2]), "=r"(r[3]) : "r"(addr));
}
// Fragment maps (g = lane>>2, t = lane&3):
//   A m16k8: a0=(g,t) a1=(g+8,t) a2=(g,t+4) a3=(g+8,t+4)
//   B k8n8 (col): b0=(k=t,col=g) b1=(k=t+4,col=g)
//   D m16n8: d0=(g,2t) d1=(g,2t+1) d2=(g+8,2t) d3=(g+8,2t+1)

// ---------------------------------------------------------------------------
// Kernel 1: fused QKV projection as ONE GEMM over N=1536.
// Grid (256, 12). Block 128x128, 8 warps = 2(M) x 4(N), warp tile 64x32.
// __launch_bounds__(256,2): cap 128 regs -> 2 CTA/SM (R8 ran 160 regs, 1 CTA).
// All ldsm addresses precomputed; k-step advance is a pure XOR (ks<<5).
// Epilogue stores tf32-rounded values (Q additionally pre-scaled by 1/sqrt(512)).
// ---------------------------------------------------------------------------
__global__ __launch_bounds__(256, 2) void qkv_tc(
    const float* __restrict__ joint,
    const float* __restrict__ Wq, const float* __restrict__ Wk, const float* __restrict__ Wv,
    const float* __restrict__ bq, const float* __restrict__ bk, const float* __restrict__ bv)
{
    const int mb  = blockIdx.x;
    const int nb  = blockIdx.y;
    const int mat = nb >> 2, h0 = (nb & 3) * 2;

    const float* W; const float* bias; float* outg;
    if (mat == 0)      { W = Wq; bias = bq; outg = g_q; }
    else if (mat == 1) { W = Wk; bias = bk; outg = g_k; }
    else               { W = Wv; bias = bv; outg = g_v; }

    __shared__ uint32_t As[128*32];   // [row][32k] chunk-swizzled
    __shared__ uint32_t Bt[128*32];   // [n][32k]   chunk-swizzled (B transposed)
    const uint32_t as_b = smem_u32(As), bt_b = smem_u32(Bt);

    const int tid  = threadIdx.x;
    const int wid  = tid >> 5, lane = tid & 31;
    const int g    = lane >> 2, t = lane & 3;
    const int wm   = (wid & 1)  * 64;
    const int wn   = (wid >> 1) * 32;

    float acc[4][4][4];
    #pragma unroll
    for (int i = 0; i < 4; i++)
        #pragma unroll
        for (int j = 0; j < 4; j++)
            #pragma unroll
            for (int r = 0; r < 4; r++) acc[i][j][r] = 0.f;

    // --- precomputed global-load addressing ---
    const float* Arow = joint + (size_t)mb * 128 * EMB_;
    const int arow = tid >> 3, akc = tid & 7;        // A: row arow+32p, chunk akc
    const float* agp = Arow + arow*EMB_ + akc*4;
    uint32_t* ast = As + arow*32 + ((akc ^ (arow & 7)) << 2);  // swizzle const in p

    const int bn  = tid & 127, bc0 = tid >> 7;       // B: col bn, chunk bc0+2p
    const int bhh = h0 + (bn >> 6), bo = bn & 63;
    const float* bgp = W + ((size_t)bhh*EMB_ + bc0*4)*OUT_ + bo;
    const int bst_w = bn*32 + ((bc0 ^ (bn & 7)) << 2);

    // --- precomputed ldsm byte addresses (k-step: ^ (ks<<5)) ---
    uint32_t a_ld[4], b_ld[2];
    {
        const int c0a = lane >> 4;
        #pragma unroll
        for (int i = 0; i < 4; i++) {
            int row = wm + i*16 + (lane & 15);
            a_ld[i] = as_b + row*128 + ((c0a ^ (row & 7)) << 4);
        }
        const int c0b = (lane >> 3) & 1;
        #pragma unroll
        for (int jj = 0; jj < 2; jj++) {
            int n = wn + (jj*2 + (lane >> 4))*8 + (lane & 7);
            b_ld[jj] = bt_b + n*128 + ((c0b ^ (n & 7)) << 4);
        }
    }

    for (int kb = 0; kb < EMB_; kb += 32) {
        #pragma unroll
        for (int p = 0; p < 4; p++) {
            float4 v = *(const float4*)(agp + p*(32*EMB_) + kb);
            uint32_t* d = ast + p*1024;
            d[0] = f2tf32(v.x); d[1] = f2tf32(v.y);
            d[2] = f2tf32(v.z); d[3] = f2tf32(v.w);
        }
        #pragma unroll
        for (int p = 0; p < 4; p++) {
            const float* wp = bgp + (kb + p*8)*OUT_;
            uint32_t* d = Bt + (bst_w ^ (p << 3));
            d[0] = f2tf32(wp[0]);       d[1] = f2tf32(wp[OUT_]);
            d[2] = f2tf32(wp[2*OUT_]);  d[3] = f2tf32(wp[3*OUT_]);
        }
        __syncthreads();

        #pragma unroll
        for (int ks = 0; ks < 4; ks++) {
            uint32_t a[4][4], b[4][2];
            #pragma unroll
            for (int i = 0; i < 4; i++)
                ldsm4(a[i], a_ld[i] ^ (ks << 5));
            #pragma unroll
            for (int jj = 0; jj < 2; jj++) {
                uint32_t r[4];
                ldsm4(r, b_ld[jj] ^ (ks << 5));
                b[jj*2][0]   = r[0]; b[jj*2][1]   = r[1];
                b[jj*2+1][0] = r[2]; b[jj*2+1][1] = r[3];
            }
            #pragma unroll
            for (int i = 0; i < 4; i++)
                #pragma unroll
                for (int j = 0; j < 4; j++)
                    mma8(acc[i][j], a[i], b[j]);
        }
        __syncthreads();
    }

    // Epilogue: + bias, tf32-round (Q pre-scaled), store to [b,h,l,o]
    const float sc = (mat == 0) ? 0.044194173824159216f : 1.0f;
    #pragma unroll
    for (int i = 0; i < 4; i++) {
        #pragma unroll
        for (int half = 0; half < 2; half++) {
            int m = mb*128 + wm + i*16 + g + half*8;
            int bb = m >> 10, l = m & 1023;
            #pragma unroll
            for (int j = 0; j < 4; j++) {
                int col = wn + j*8 + t*2;
                int h = h0 + (col >> 6), o = col & 63;
                float2 r;
                r.x = __uint_as_float(f2tf32((acc[i][j][half*2+0] + __ldg(bias + h*OUT_ + o))     * sc));
                r.y = __uint_as_float(f2tf32((acc[i][j][half*2+1] + __ldg(bias + h*OUT_ + o + 1)) * sc));
                *(float2*)(outg + ((size_t)(bb*H_ + h)*L_ + l)*OUT_ + o) = r;
            }
        }
    }
}

// ---------------------------------------------------------------------------
// Kernel 2: attention, tf32 MMA + ldmatrix. Block = one (b,h) x 128 q-rows.
// Inputs are tf32-pre-rounded (Q pre-scaled) -> tile loads are RAW bit copies
// (no cvt, no scale FMA in the serialized load phases).
// ---------------------------------------------------------------------------
#define PS_OFF 0                      // P [128 rows][128 k]  64KB (Q staging aliases)
#define KS_OFF 65536                  // K [128 key][64 k]    32KB
#define VT_OFF 98304                  // Vt [64 o][128 key]   32KB
#define LB_OFF 131072                 // l partials [128][2]  1KB
#define SMEM_ATTN 132096

__global__ __launch_bounds__(256, 1) void attn_tc(const int* __restrict__ traj)
{
    extern __shared__ char smem[];
    uint32_t* Ps = (uint32_t*)(smem + PS_OFF);
    uint32_t* Ks = (uint32_t*)(smem + KS_OFF);
    uint32_t* Vt = (uint32_t*)(smem + VT_OFF);
    float*    Lb = (float*)(smem + LB_OFF);
    const uint32_t ps_b = smem_u32(Ps), ks_b = smem_u32(Ks), vt_b = smem_u32(Vt);

    const int qb = blockIdx.x;          // 8 q-tiles of 128 rows
    const int bh = blockIdx.y;          // 256
    const int b  = bh >> 3, h = bh & 7;

    const int tid  = threadIdx.x;
    const int wid  = tid >> 5, lane = tid & 31;
    const int g    = lane >> 2, t = lane & 3;
    const int wm   = (wid >> 1) * 32;   // M stripe (S and O)
    const int wnS  = (wid & 1)  * 64;   // S columns
    const int wnO  = (wid & 1)  * 32;   // O columns

    // traj_len dtype sniff (int64 -> odd int32 words zero; values < 1024)
    int is64 = 1;
    #pragma unroll
    for (int i = 1; i < 32; i += 2) is64 &= (traj[i] == 0);
    const int T = is64 ? traj[2*b] : traj[b];

    // Stage Q [128,64] into Ps region (raw copy: already scaled + tf32-rounded)
    const uint4* Qg = (const uint4*)(g_q + (size_t)bh * L_ * OUT_ + (size_t)(qb*128) * OUT_);
    #pragma unroll
    for (int p = 0; p < 8; p++) {
        int task = tid + p*256;
        int row = task >> 4, kc = task & 15;
        *(uint4*)(Ps + row*64 + ((kc ^ (row & 7)) << 2)) = Qg[row*16 + kc];
    }
    __syncthreads();

    // Hoist Q fragments: [i=2 m16 tiles][8 ks][4 regs]
    uint32_t qf[2][8][4];
    #pragma unroll
    for (int i = 0; i < 2; i++)
        #pragma unroll
        for (int ks = 0; ks < 8; ks++) {
            int row = wm + i*16 + (lane & 15);
            int kc  = ks*2 + (lane >> 4);
            ldsm4(qf[i][ks], ps_b + ((row*64 + ((kc ^ (row & 7)) << 2)) << 2));
        }
    __syncthreads();   // Q reads complete before P overwrites the region

    float oacc[2][4][4];
    #pragma unroll
    for (int i = 0; i < 2; i++)
        #pragma unroll
        for (int j = 0; j < 4; j++)
            #pragma unroll
            for (int r = 0; r < 4; r++) oacc[i][j][r] = 0.f;
    float lp[2][2] = {{0.f,0.f},{0.f,0.f}};
    bool qv[2][2];
    #pragma unroll
    for (int i = 0; i < 2; i++) {
        qv[i][0] = (qb*128 + wm + i*16 + g)     < T;
        qv[i][1] = (qb*128 + wm + i*16 + g + 8) < T;
    }

    const uint4* Kg = (const uint4*)(g_k + (size_t)bh * L_ * OUT_);
    const uint4* Vg = (const uint4*)(g_v + (size_t)bh * L_ * OUT_);

    for (int kb = 0; kb < L_; kb += 128) {
        // K tile [128 key][64 k] — raw copy
        #pragma unroll
        for (int p = 0; p < 8; p++) {
            int task = tid + p*256;
            int key = task >> 4, kc = task & 15;
            *(uint4*)(Ks + key*64 + ((kc ^ (key & 7)) << 2)) =
                Kg[(size_t)(kb + key)*16 + kc];
        }
        // V transposed -> Vt [64 o][128 key] — raw bits
        #pragma unroll
        for (int p = 0; p < 8; p++) {
            int task = tid + p*256;
            int key = task >> 4, o4 = task & 15;
            uint4 v = Vg[(size_t)(kb + key)*16 + o4];
            int kcv = key >> 2, kr = key & 3;
            uint32_t vv[4] = {v.x, v.y, v.z, v.w};
            #pragma unroll
            for (int e = 0; e < 4; e++) {
                int o = o4*4 + e;
                Vt[o*128 + ((kcv ^ (o & 7)) << 2) + kr] = vv[e];
            }
        }
        __syncthreads();

        // S = Q K^T : warp 32(M) x 64(N), k = 64
        float sacc[2][8][4];
        #pragma unroll
        for (int i = 0; i < 2; i++)
            #pragma unroll
            for (int j = 0; j < 8; j++)
                #pragma unroll
                for (int r = 0; r < 4; r++) sacc[i][j][r] = 0.f;

        #pragma unroll
        for (int ks = 0; ks < 8; ks++) {
            uint32_t bk[8][2];
            #pragma unroll
            for (int jj = 0; jj < 4; jj++) {
                int key = wnS + (jj*2 + (lane >> 4))*8 + (lane & 7);
                int kc  = ks*2 + ((lane >> 3) & 1);
                uint32_t r[4];
                ldsm4(r, ks_b + ((key*64 + ((kc ^ (key & 7)) << 2)) << 2));
                bk[jj*2][0]   = r[0]; bk[jj*2][1]   = r[1];
                bk[jj*2+1][0] = r[2]; bk[jj*2+1][1] = r[3];
            }
            #pragma unroll
            for (int i = 0; i < 2; i++)
                #pragma unroll
                for (int j = 0; j < 8; j++)
                    mma8(sacc[i][j], qf[i][ks], bk[j]);
        }

        // mask + exp, accumulate l, store P (tf32, swizzled)
        #pragma unroll
        for (int j = 0; j < 8; j++) {
            int col = wnS + j*8 + t*2;
            bool kv0 = (kb + col)     < T;
            bool kv1 = (kb + col + 1) < T;
            #pragma unroll
            for (int i = 0; i < 2; i++) {
                #pragma unroll
                for (int half = 0; half < 2; half++) {
                    int row = wm + i*16 + g + half*8;
                    float p0 = __expf((qv[i][half] && kv0) ? sacc[i][j][half*2+0] : 0.f);
                    float p1 = __expf((qv[i][half] && kv1) ? sacc[i][j][half*2+1] : 0.f);
                    lp[i][half] += p0 + p1;
                    uint32_t* dst = Ps + row*128 + (((col >> 2) ^ (row & 7)) << 2) + (col & 3);
                    dst[0] = f2tf32(p0);
                    dst[1] = f2tf32(p1);
                }
            }
        }
        __syncthreads();   // P complete before PV

        // O += P V : warp 32(M) x 32(N), k = 128
        #pragma unroll
        for (int ks = 0; ks < 16; ks++) {
            uint32_t pa[2][4], vb[4][2];
            #pragma unroll
            for (int i = 0; i < 2; i++) {
                int row = wm + i*16 + (lane & 15);
                int kc  = ks*2 + (lane >> 4);
                ldsm4(pa[i], ps_b + ((row*128 + ((kc ^ (row & 7)) << 2)) << 2));
            }
            #pragma unroll
            for (int jj = 0; jj < 2; jj++) {
                int o  = wnO + (jj*2 + (lane >> 4))*8 + (lane & 7);
                int kc = ks*2 + ((lane >> 3) & 1);
                uint32_t r[4];
                ldsm4(r, vt_b + ((o*128 + ((kc ^ (o & 7)) << 2)) << 2));
                vb[jj*2][0]   = r[0]; vb[jj*2][1]   = r[1];
                vb[jj*2+1][0] = r[2]; vb[jj*2+1][1] = r[3];
            }
            #pragma unroll
            for (int i = 0; i < 2; i++)
                #pragma unroll
                for (int j = 0; j < 4; j++)
                    mma8(oacc[i][j], pa[i], vb[j]);
        }
        __syncthreads();   // PV reads done before next tile overwrite
    }

    // Reduce l within quad, publish across the two N-col warps
    #pragma unroll
    for (int i = 0; i < 2; i++)
        #pragma unroll
        for (int half = 0; half < 2; half++) {
            float v = lp[i][half];
            v += __shfl_xor_sync(0xffffffffu, v, 1);
            v += __shfl_xor_sync(0xffffffffu, v, 2);
            if (t == 0) Lb[(wm + i*16 + g + half*8)*2 + (wid & 1)] = v;
        }
    __syncthreads();

    // Normalize O, tf32-round, store concat [b,l,h*o]
    #pragma unroll
    for (int i = 0; i < 2; i++) {
        #pragma unroll
        for (int half = 0; half < 2; half++) {
            int row = wm + i*16 + g + half*8;
            float inv = 1.0f / (Lb[row*2] + Lb[row*2+1]);
            int q = qb*128 + row;
            float* dst = g_c + ((size_t)(b*L_ + q)*H_ + h) * OUT_;
            #pragma unroll
            for (int j = 0; j < 4; j++) {
                int col = wnO + j*8 + t*2;
                float2 r;
                r.x = __uint_as_float(f2tf32(oacc[i][j][half*2+0] * inv));
                r.y = __uint_as_float(f2tf32(oacc[i][j][half*2+1] * inv));
                *(float2*)(dst + col) = r;
            }
        }
    }
}

// ---------------------------------------------------------------------------
// Kernel 3: output projection  concat[32768,512] @ Wo[512,64], tf32 MMA.
// A side (g_c) is pre-rounded -> raw copy; only Wo needs cvt.
// ---------------------------------------------------------------------------
__global__ __launch_bounds__(256) void out_tc(
    const float* __restrict__ Wo, float* __restrict__ outp)
{
    const int mb = blockIdx.x;

    __shared__ uint32_t As[128][36];
    __shared__ uint32_t Bs[32][72];

    const int tid  = threadIdx.x;
    const int wid  = tid >> 5, lane = tid & 31;
    const int g    = lane >> 2, t = lane & 3;
    const int wm   = (wid & 3) * 32;
    const int wn   = (wid >> 2) * 32;

    float acc[2][4][4];
    #pragma unroll
    for (int i = 0; i < 2; i++)
        #pragma unroll
        for (int j = 0; j < 4; j++)
            #pragma unroll
            for (int r = 0; r < 4; r++) acc[i][j][r] = 0.f;

    const float* Abase = g_c + (size_t)mb * 128 * (H_*OUT_);

    for (int kb = 0; kb < H_*OUT_; kb += 32) {
        #pragma unroll
        for (int f = tid; f < 1024; f += 256) {
            int row = f >> 3, c4 = (f & 7) << 2;
            uint4 v = *(const uint4*)(Abase + row * (H_*OUT_) + kb + c4);
            As[row][c4+0] = v.x; As[row][c4+1] = v.y;
            As[row][c4+2] = v.z; As[row][c4+3] = v.w;
        }
        #pragma unroll
        for (int f = tid; f < 512; f += 256) {
            int row = f >> 4, c4 = (f & 15) << 2;
            float4 v = *(const float4*)(Wo + (kb + row) * OUT_ + c4);
            Bs[row][c4+0] = f2tf32(v.x); Bs[row][c4+1] = f2tf32(v.y);
            Bs[row][c4+2] = f2tf32(v.z); Bs[row][c4+3] = f2tf32(v.w);
        }
        __syncthreads();

        #pragma unroll
        for (int ks = 0; ks < 4; ks++) {
            const int k0 = ks * 8;
            uint32_t a[2][4], b[4][2];
            #pragma unroll
            for (int i = 0; i < 2; i++) {
                int r0 = wm + i*16 + g;
                a[i][0] = As[r0][k0 + t];     a[i][1] = As[r0+8][k0 + t];
                a[i][2] = As[r0][k0 + t + 4]; a[i][3] = As[r0+8][k0 + t + 4];
            }
            #pragma unroll
            for (int j = 0; j < 4; j++) {
                int c = wn + j*8 + g;
                b[j][0] = Bs[k0 + t][c];
                b[j][1] = Bs[k0 + t + 4][c];
            }
            #pragma unroll
            for (int i = 0; i < 2; i++)
                #pragma unroll
                for (int j = 0; j < 4; j++)
                    mma8(acc[i][j], a[i], b[j]);
        }
        __syncthreads();
    }

    #pragma unroll
    for (int i = 0; i < 2; i++) {
        #pragma unroll
        for (int half = 0; half < 2; half++) {
            int m = mb*128 + wm + i*16 + g + half*8;
            float* dst = outp + (size_t)m * OUT_;
            #pragma unroll
            for (int j = 0; j < 4; j++) {
                int c = wn + j*8 + t*2;
                float2 r;
                r.x = acc[i][j][half*2+0];
                r.y = acc[i][j][half*2+1];
                *(float2*)(dst + c) = r;
            }
        }
    }
}

// ---------------------------------------------------------------------------
extern "C" void kernel_launch(void* const* d_in, const int* in_sizes, int n_in,
                              void* d_out, int out_size)
{
    const float* joint = (const float*)d_in[0];
    // d_in[1] = delta [B,L,L,2] -- unused by the reference math (mask shape only)
    const int*   traj  = (const int*)d_in[2];
    const float* Wq    = (const float*)d_in[3];
    const float* Wk    = (const float*)d_in[4];
    const float* Wv    = (const float*)d_in[5];
    const float* bq    = (const float*)d_in[6];
    const float* bk    = (const float*)d_in[7];
    const float* bv    = (const float*)d_in[8];
    const float* Wo    = (const float*)d_in[9];
    float* out = (float*)d_out;

    static int attr_set = 0;
    if (!attr_set) {
        cudaFuncSetAttribute(attn_tc,
            cudaFuncAttributeMaxDynamicSharedMemorySize, SMEM_ATTN);
        attr_set = 1;
    }

    dim3 g1(256, 12);
    qkv_tc<<<g1, 256>>>(joint, Wq, Wk, Wv, bq, bk, bv);

    dim3 g2(8, 256);
    attn_tc<<<g2, 256, SMEM_ATTN>>>(traj);

    out_tc<<<256, 256>>>(Wo, out);
}

// round 14
// speedup vs baseline: 1.3177x; 1.1590x over previous
#include <cuda_runtime.h>
#include <cstdint>

#define B_   32
#define L_   1024
#define EMB_ 512
#define OUT_ 64
#define H_   8

// Scratch (device globals: allocation-free per harness rules)
// g_q/g_k/g_v/g_c hold tf32-pre-rounded fp32 bit patterns (g_q also pre-scaled).
__device__ float g_q[B_*H_*L_*OUT_];   // [b,h,l,o]
__device__ float g_k[B_*H_*L_*OUT_];   // [b,h,l,o]
__device__ float g_v[B_*H_*L_*OUT_];   // [b,h,l,o]
__device__ float g_c[B_*L_*H_*OUT_];   // concat [b,l,h*o]

// ===========================================================================
// tf32 warp-MMA helpers (baseline PTX, valid on plain sm_103 target)
// ===========================================================================
__device__ __forceinline__ uint32_t f2tf32(float x) {
    uint32_t r;
    asm("cvt.rna.tf32.f32 %0, %1;" : "=r"(r) : "f"(x));
    return r;
}
__device__ __forceinline__ uint32_t smem_u32(const void* p) {
    uint32_t a;
    asm("{ .reg .u64 t; cvta.to.shared.u64 t, %1; cvt.u32.u64 %0, t; }"
        : "=r"(a) : "l"(p));
    return a;
}
// D(16x8,f32) += A(16x8,tf32,row) * B(8x8,tf32,col)
__device__ __forceinline__ void mma8(float* d, const uint32_t* a, const uint32_t* b) {
    asm volatile(
        "mma.sync.aligned.m16n8k8.row.col.f32.tf32.tf32.f32 "
        "{%0,%1,%2,%3}, {%4,%5,%6,%7}, {%8,%9}, {%0,%1,%2,%3};"
        : "+f"(d[0]), "+f"(d[1]), "+f"(d[2]), "+f"(d[3])
        : "r"(a[0]), "r"(a[1]), "r"(a[2]), "r"(a[3]), "r"(b[0]), "r"(b[1]));
}
__device__ __forceinline__ void ldsm4(uint32_t* r, uint32_t addr) {
    asm volatile("ldmatrix.sync.aligned.m8n8.x4.shared.b16 {%0,%1,%2,%3}, [%4];"
        : "=r"(r[0]), "=r"(r[1]), "=r"(r[2]), "=r"(r[3]) : "r"(addr));
}
// Fragment maps (g = lane>>2, t = lane&3):
//   A m16k8: a0=(g,t) a1=(g+8,t) a2=(g,t+4) a3=(g+8,t+4)
//   B k8n8 (col): b0=(k=t,col=g) b1=(k=t+4,col=g)
//   D m16n8: d0=(g,2t) d1=(g,2t+1) d2=(g+8,2t) d3=(g+8,2t+1)

// ---------------------------------------------------------------------------
// Kernel 1: fused QKV projection as ONE GEMM over N=1536.  (unchanged R11)
// ---------------------------------------------------------------------------
__global__ __launch_bounds__(256, 2) void qkv_tc(
    const float* __restrict__ joint,
    const float* __restrict__ Wq, const float* __restrict__ Wk, const float* __restrict__ Wv,
    const float* __restrict__ bq, const float* __restrict__ bk, const float* __restrict__ bv)
{
    const int mb  = blockIdx.x;
    const int nb  = blockIdx.y;
    const int mat = nb >> 2, h0 = (nb & 3) * 2;

    const float* W; const float* bias; float* outg;
    if (mat == 0)      { W = Wq; bias = bq; outg = g_q; }
    else if (mat == 1) { W = Wk; bias = bk; outg = g_k; }
    else               { W = Wv; bias = bv; outg = g_v; }

    __shared__ uint32_t As[128*32];   // [row][32k] chunk-swizzled
    __shared__ uint32_t Bt[128*32];   // [n][32k]   chunk-swizzled (B transposed)
    const uint32_t as_b = smem_u32(As), bt_b = smem_u32(Bt);

    const int tid  = threadIdx.x;
    const int wid  = tid >> 5, lane = tid & 31;
    const int g    = lane >> 2, t = lane & 3;
    const int wm   = (wid & 1)  * 64;
    const int wn   = (wid >> 1) * 32;

    float acc[4][4][4];
    #pragma unroll
    for (int i = 0; i < 4; i++)
        #pragma unroll
        for (int j = 0; j < 4; j++)
            #pragma unroll
            for (int r = 0; r < 4; r++) acc[i][j][r] = 0.f;

    const float* Arow = joint + (size_t)mb * 128 * EMB_;
    const int arow = tid >> 3, akc = tid & 7;
    const float* agp = Arow + arow*EMB_ + akc*4;
    uint32_t* ast = As + arow*32 + ((akc ^ (arow & 7)) << 2);

    const int bn  = tid & 127, bc0 = tid >> 7;
    const int bhh = h0 + (bn >> 6), bo = bn & 63;
    const float* bgp = W + ((size_t)bhh*EMB_ + bc0*4)*OUT_ + bo;
    const int bst_w = bn*32 + ((bc0 ^ (bn & 7)) << 2);

    uint32_t a_ld[4], b_ld[2];
    {
        const int c0a = lane >> 4;
        #pragma unroll
        for (int i = 0; i < 4; i++) {
            int row = wm + i*16 + (lane & 15);
            a_ld[i] = as_b + row*128 + ((c0a ^ (row & 7)) << 4);
        }
        const int c0b = (lane >> 3) & 1;
        #pragma unroll
        for (int jj = 0; jj < 2; jj++) {
            int n = wn + (jj*2 + (lane >> 4))*8 + (lane & 7);
            b_ld[jj] = bt_b + n*128 + ((c0b ^ (n & 7)) << 4);
        }
    }

    for (int kb = 0; kb < EMB_; kb += 32) {
        #pragma unroll
        for (int p = 0; p < 4; p++) {
            float4 v = *(const float4*)(agp + p*(32*EMB_) + kb);
            uint32_t* d = ast + p*1024;
            d[0] = f2tf32(v.x); d[1] = f2tf32(v.y);
            d[2] = f2tf32(v.z); d[3] = f2tf32(v.w);
        }
        #pragma unroll
        for (int p = 0; p < 4; p++) {
            const float* wp = bgp + (kb + p*8)*OUT_;
            uint32_t* d = Bt + (bst_w ^ (p << 3));
            d[0] = f2tf32(wp[0]);       d[1] = f2tf32(wp[OUT_]);
            d[2] = f2tf32(wp[2*OUT_]);  d[3] = f2tf32(wp[3*OUT_]);
        }
        __syncthreads();

        #pragma unroll
        for (int ks = 0; ks < 4; ks++) {
            uint32_t a[4][4], b[4][2];
            #pragma unroll
            for (int i = 0; i < 4; i++)
                ldsm4(a[i], a_ld[i] ^ (ks << 5));
            #pragma unroll
            for (int jj = 0; jj < 2; jj++) {
                uint32_t r[4];
                ldsm4(r, b_ld[jj] ^ (ks << 5));
                b[jj*2][0]   = r[0]; b[jj*2][1]   = r[1];
                b[jj*2+1][0] = r[2]; b[jj*2+1][1] = r[3];
            }
            #pragma unroll
            for (int i = 0; i < 4; i++)
                #pragma unroll
                for (int j = 0; j < 4; j++)
                    mma8(acc[i][j], a[i], b[j]);
        }
        __syncthreads();
    }

    const float sc = (mat == 0) ? 0.044194173824159216f : 1.0f;
    #pragma unroll
    for (int i = 0; i < 4; i++) {
        #pragma unroll
        for (int half = 0; half < 2; half++) {
            int m = mb*128 + wm + i*16 + g + half*8;
            int bb = m >> 10, l = m & 1023;
            #pragma unroll
            for (int j = 0; j < 4; j++) {
                int col = wn + j*8 + t*2;
                int h = h0 + (col >> 6), o = col & 63;
                float2 r;
                r.x = __uint_as_float(f2tf32((acc[i][j][half*2+0] + __ldg(bias + h*OUT_ + o))     * sc));
                r.y = __uint_as_float(f2tf32((acc[i][j][half*2+1] + __ldg(bias + h*OUT_ + o + 1)) * sc));
                *(float2*)(outg + ((size_t)(bb*H_ + h)*L_ + l)*OUT_ + o) = r;
            }
        }
    }
}

// ---------------------------------------------------------------------------
// Kernel 2: attention v3 — 64-key tiles, 99KB smem -> 2 CTA/SM (occ 25%).
// Block = one (b,h) x 128 q-rows, 8 warps = 4(M) x 2(N), warp tiles 32x32.
// V kept ROW-major (stride 72: conflict-free scalar B-frag loads 8t+g) —
// eliminates the 8-way-conflicted Vt transpose stores of R11.
// Q in its own smem buffer (no reg hoist: stays under 128 regs for 2 CTAs).
// ---------------------------------------------------------------------------
#define QS_OFF 0                      // Q  [128][64]      32KB
#define PS_OFF 32768                  // P  [128][64]      32KB
#define KS_OFF 65536                  // K  [64][64]       16KB
#define VS_OFF 81920                  // V  [64][72]       18KB
#define LB_OFF 100352                 // l partials [128][2] 1KB
#define SMEM_ATTN 101376

__global__ __launch_bounds__(256, 2) void attn_tc(const int* __restrict__ traj)
{
    extern __shared__ char smem[];
    uint32_t* Qs = (uint32_t*)(smem + QS_OFF);
    uint32_t* Ps = (uint32_t*)(smem + PS_OFF);
    uint32_t* Ks = (uint32_t*)(smem + KS_OFF);
    uint32_t* Vs = (uint32_t*)(smem + VS_OFF);
    float*    Lb = (float*)(smem + LB_OFF);
    const uint32_t qs_b = smem_u32(Qs), ps_b = smem_u32(Ps), ks_b = smem_u32(Ks);

    const int qb = blockIdx.x;          // 8 q-tiles of 128 rows
    const int bh = blockIdx.y;          // 256
    const int b  = bh >> 3, h = bh & 7;

    const int tid  = threadIdx.x;
    const int wid  = tid >> 5, lane = tid & 31;
    const int g    = lane >> 2, t = lane & 3;
    const int wm   = (wid >> 1) * 32;   // M stripe (S and O)
    const int wnS  = (wid & 1)  * 32;   // S columns (32-key window)
    const int wnO  = (wid & 1)  * 32;   // O columns

    // traj_len dtype sniff (int64 -> odd int32 words zero; values < 1024)
    int is64 = 1;
    #pragma unroll
    for (int i = 1; i < 32; i += 2) is64 &= (traj[i] == 0);
    const int T = is64 ? traj[2*b] : traj[b];

    // Stage Q [128,64] (raw copy: already scaled + tf32-rounded)
    const uint4* Qg = (const uint4*)(g_q + (size_t)bh * L_ * OUT_ + (size_t)(qb*128) * OUT_);
    #pragma unroll
    for (int p = 0; p < 8; p++) {
        int task = tid + p*256;
        int row = task >> 4, kc = task & 15;
        *(uint4*)(Qs + row*64 + ((kc ^ (row & 7)) << 2)) = Qg[row*16 + kc];
    }
    __syncthreads();

    float oacc[2][4][4];
    #pragma unroll
    for (int i = 0; i < 2; i++)
        #pragma unroll
        for (int j = 0; j < 4; j++)
            #pragma unroll
            for (int r = 0; r < 4; r++) oacc[i][j][r] = 0.f;
    float lp[2][2] = {{0.f,0.f},{0.f,0.f}};
    bool qv[2][2];
    #pragma unroll
    for (int i = 0; i < 2; i++) {
        qv[i][0] = (qb*128 + wm + i*16 + g)     < T;
        qv[i][1] = (qb*128 + wm + i*16 + g + 8) < T;
    }

    const uint4* Kg = (const uint4*)(g_k + (size_t)bh * L_ * OUT_);
    const uint4* Vg = (const uint4*)(g_v + (size_t)bh * L_ * OUT_);

    for (int kb = 0; kb < L_; kb += 64) {
        // K tile [64 key][64 k] — raw copy, chunk-swizzled
        #pragma unroll
        for (int p = 0; p < 4; p++) {
            int task = tid + p*256;
            int key = task >> 4, kc = task & 15;
            *(uint4*)(Ks + key*64 + ((kc ^ (key & 7)) << 2)) =
                Kg[(size_t)(kb + key)*16 + kc];
        }
        // V tile [64 key][72-stride] — raw copy, ROW-major (no transpose)
        #pragma unroll
        for (int p = 0; p < 4; p++) {
            int task = tid + p*256;
            int key = task >> 4, o4 = task & 15;
            *(uint4*)(Vs + key*72 + o4*4) = Vg[(size_t)(kb + key)*16 + o4];
        }
        __syncthreads();

        // S = Q K^T : warp 32(M) x 32(N), k = 64
        float sacc[2][4][4];
        #pragma unroll
        for (int i = 0; i < 2; i++)
            #pragma unroll
            for (int j = 0; j < 4; j++)
                #pragma unroll
                for (int r = 0; r < 4; r++) sacc[i][j][r] = 0.f;

        #pragma unroll
        for (int ks = 0; ks < 8; ks++) {
            uint32_t aq[2][4], bk[4][2];
            #pragma unroll
            for (int i = 0; i < 2; i++) {
                int row = wm + i*16 + (lane & 15);
                int kc  = ks*2 + (lane >> 4);
                ldsm4(aq[i], qs_b + ((row*64 + ((kc ^ (row & 7)) << 2)) << 2));
            }
            {
                int key = wnS + ((lane >> 4))*8 + (lane & 7);      // jj=0
                int kc  = ks*2 + ((lane >> 3) & 1);
                uint32_t r[4];
                ldsm4(r, ks_b + ((key*64 + ((kc ^ (key & 7)) << 2)) << 2));
                bk[0][0] = r[0]; bk[0][1] = r[1];
                bk[1][0] = r[2]; bk[1][1] = r[3];
            }
            {
                int key = wnS + (2 + (lane >> 4))*8 + (lane & 7);  // jj=1
                int kc  = ks*2 + ((lane >> 3) & 1);
                uint32_t r[4];
                ldsm4(r, ks_b + ((key*64 + ((kc ^ (key & 7)) << 2)) << 2));
                bk[2][0] = r[0]; bk[2][1] = r[1];
                bk[3][0] = r[2]; bk[3][1] = r[3];
            }
            #pragma unroll
            for (int i = 0; i < 2; i++)
                #pragma unroll
                for (int j = 0; j < 4; j++)
                    mma8(sacc[i][j], aq[i], bk[j]);
        }

        // mask + exp, accumulate l, store P (tf32, swizzled, stride 64)
        #pragma unroll
        for (int j = 0; j < 4; j++) {
            int col = wnS + j*8 + t*2;
            bool kv0 = (kb + col)     < T;
            bool kv1 = (kb + col + 1) < T;
            #pragma unroll
            for (int i = 0; i < 2; i++) {
                #pragma unroll
                for (int half = 0; half < 2; half++) {
                    int row = wm + i*16 + g + half*8;
                    float p0 = __expf((qv[i][half] && kv0) ? sacc[i][j][half*2+0] : 0.f);
                    float p1 = __expf((qv[i][half] && kv1) ? sacc[i][j][half*2+1] : 0.f);
                    lp[i][half] += p0 + p1;
                    uint32_t* dst = Ps + row*64 + (((col >> 2) ^ (row & 7)) << 2) + (col & 3);
                    dst[0] = f2tf32(p0);
                    dst[1] = f2tf32(p1);
                }
            }
        }
        __syncthreads();   // P complete before PV

        // O += P V : warp 32(M) x 32(N), k = 64 keys
        #pragma unroll
        for (int ks = 0; ks < 8; ks++) {
            uint32_t pa[2][4], vbf[4][2];
            #pragma unroll
            for (int i = 0; i < 2; i++) {
                int row = wm + i*16 + (lane & 15);
                int kc  = ks*2 + (lane >> 4);
                ldsm4(pa[i], ps_b + ((row*64 + ((kc ^ (row & 7)) << 2)) << 2));
            }
            const int kr0 = (ks*8 + t)*72, kr1 = (ks*8 + t + 4)*72;
            #pragma unroll
            for (int j = 0; j < 4; j++) {
                int o = wnO + j*8 + g;
                vbf[j][0] = Vs[kr0 + o];    // conflict-free: bank = 8t+g+const
                vbf[j][1] = Vs[kr1 + o];
            }
            #pragma unroll
            for (int i = 0; i < 2; i++)
                #pragma unroll
                for (int j = 0; j < 4; j++)
                    mma8(oacc[i][j], pa[i], vbf[j]);
        }
        __syncthreads();   // PV/S reads done before next tile overwrite
    }

    // Reduce l within quad, publish across the two N-col warps
    #pragma unroll
    for (int i = 0; i < 2; i++)
        #pragma unroll
        for (int half = 0; half < 2; half++) {
            float v = lp[i][half];
            v += __shfl_xor_sync(0xffffffffu, v, 1);
            v += __shfl_xor_sync(0xffffffffu, v, 2);
            if (t == 0) Lb[(wm + i*16 + g + half*8)*2 + (wid & 1)] = v;
        }
    __syncthreads();

    // Normalize O, tf32-round, store concat [b,l,h*o]
    #pragma unroll
    for (int i = 0; i < 2; i++) {
        #pragma unroll
        for (int half = 0; half < 2; half++) {
            int row = wm + i*16 + g + half*8;
            float inv = 1.0f / (Lb[row*2] + Lb[row*2+1]);
            int q = qb*128 + row;
            float* dst = g_c + ((size_t)(b*L_ + q)*H_ + h) * OUT_;
            #pragma unroll
            for (int j = 0; j < 4; j++) {
                int col = wnO + j*8 + t*2;
                float2 r;
                r.x = __uint_as_float(f2tf32(oacc[i][j][half*2+0] * inv));
                r.y = __uint_as_float(f2tf32(oacc[i][j][half*2+1] * inv));
                *(float2*)(dst + col) = r;
            }
        }
    }
}

// ---------------------------------------------------------------------------
// Kernel 3: output projection  concat[32768,512] @ Wo[512,64], tf32 MMA.
// (unchanged R11: A side raw copy, Wo cvt)
// ---------------------------------------------------------------------------
__global__ __launch_bounds__(256) void out_tc(
    const float* __restrict__ Wo, float* __restrict__ outp)
{
    const int mb = blockIdx.x;

    __shared__ uint32_t As[128][36];
    __shared__ uint32_t Bs[32][72];

    const int tid  = threadIdx.x;
    const int wid  = tid >> 5, lane = tid & 31;
    const int g    = lane >> 2, t = lane & 3;
    const int wm   = (wid & 3) * 32;
    const int wn   = (wid >> 2) * 32;

    float acc[2][4][4];
    #pragma unroll
    for (int i = 0; i < 2; i++)
        #pragma unroll
        for (int j = 0; j < 4; j++)
            #pragma unroll
            for (int r = 0; r < 4; r++) acc[i][j][r] = 0.f;

    const float* Abase = g_c + (size_t)mb * 128 * (H_*OUT_);

    for (int kb = 0; kb < H_*OUT_; kb += 32) {
        #pragma unroll
        for (int f = tid; f < 1024; f += 256) {
            int row = f >> 3, c4 = (f & 7) << 2;
            uint4 v = *(const uint4*)(Abase + row * (H_*OUT_) + kb + c4);
            As[row][c4+0] = v.x; As[row][c4+1] = v.y;
            As[row][c4+2] = v.z; As[row][c4+3] = v.w;
        }
        #pragma unroll
        for (int f = tid; f < 512; f += 256) {
            int row = f >> 4, c4 = (f & 15) << 2;
            float4 v = *(const float4*)(Wo + (kb + row) * OUT_ + c4);
            Bs[row][c4+0] = f2tf32(v.x); Bs[row][c4+1] = f2tf32(v.y);
            Bs[row][c4+2] = f2tf32(v.z); Bs[row][c4+3] = f2tf32(v.w);
        }
        __syncthreads();

        #pragma unroll
        for (int ks = 0; ks < 4; ks++) {
            const int k0 = ks * 8;
            uint32_t a[2][4], b[4][2];
            #pragma unroll
            for (int i = 0; i < 2; i++) {
                int r0 = wm + i*16 + g;
                a[i][0] = As[r0][k0 + t];     a[i][1] = As[r0+8][k0 + t];
                a[i][2] = As[r0][k0 + t + 4]; a[i][3] = As[r0+8][k0 + t + 4];
            }
            #pragma unroll
            for (int j = 0; j < 4; j++) {
                int c = wn + j*8 + g;
                b[j][0] = Bs[k0 + t][c];
                b[j][1] = Bs[k0 + t + 4][c];
            }
            #pragma unroll
            for (int i = 0; i < 2; i++)
                #pragma unroll
                for (int j = 0; j < 4; j++)
                    mma8(acc[i][j], a[i], b[j]);
        }
        __syncthreads();
    }

    #pragma unroll
    for (int i = 0; i < 2; i++) {
        #pragma unroll
        for (int half = 0; half < 2; half++) {
            int m = mb*128 + wm + i*16 + g + half*8;
            float* dst = outp + (size_t)m * OUT_;
            #pragma unroll
            for (int j = 0; j < 4; j++) {
                int c = wn + j*8 + t*2;
                float2 r;
                r.x = acc[i][j][half*2+0];
                r.y = acc[i][j][half*2+1];
                *(float2*)(dst + c) = r;
            }
        }
    }
}

// ---------------------------------------------------------------------------
extern "C" void kernel_launch(void* const* d_in, const int* in_sizes, int n_in,
                              void* d_out, int out_size)
{
    const float* joint = (const float*)d_in[0];
    // d_in[1] = delta [B,L,L,2] -- unused by the reference math (mask shape only)
    const int*   traj  = (const int*)d_in[2];
    const float* Wq    = (const float*)d_in[3];
    const float* Wk    = (const float*)d_in[4];
    const float* Wv    = (const float*)d_in[5];
    const float* bq    = (const float*)d_in[6];
    const float* bk    = (const float*)d_in[7];
    const float* bv    = (const float*)d_in[8];
    const float* Wo    = (const float*)d_in[9];
    float* out = (float*)d_out;

    static int attr_set = 0;
    if (!attr_set) {
        cudaFuncSetAttribute(attn_tc,
            cudaFuncAttributeMaxDynamicSharedMemorySize, SMEM_ATTN);
        attr_set = 1;
    }

    dim3 g1(256, 12);
    qkv_tc<<<g1, 256>>>(joint, Wq, Wk, Wv, bq, bk, bv);

    dim3 g2(8, 256);
    attn_tc<<<g2, 256, SMEM_ATTN>>>(traj);

    out_tc<<<256, 256>>>(Wo, out);
}